// round 6
// baseline (speedup 1.0000x reference)
#include <cuda_runtime.h>
#include <math.h>

#define NMAX 50000
#define EMAX 500000

// ---------------- static scratch ------------------------------------------
__device__ float g_XN[NMAX * 128];
__device__ float g_Q[NMAX * 128];
__device__ float g_K[NMAX * 128];
__device__ float g_V[NMAX * 128];
__device__ float g_AGG[NMAX * 128];
__device__ float g_XMID[NMAX * 128];
__device__ float g_FFNH[NMAX * 256];
__device__ float g_LOG[EMAX * 8];
__device__ float g_ATT[EMAX * 8];
__device__ float g_WS[EMAX * 128];
__device__ int   g_perm[EMAX];
__device__ int   g_srcs[EMAX];
__device__ int   g_dsts[EMAX];
__device__ int   g_cnt[NMAX];
__device__ int   g_rowstart[NMAX + 1];
__device__ int   g_cursor[NMAX];
__device__ int   g_bsum[256];
__device__ int   g_bsumex[256];

__device__ __forceinline__ float gelu_f(float x) {
    return 0.5f * x * (1.0f + erff(x * 0.70710678118654752f));
}
__device__ __forceinline__ float sigmoid_f(float x) {
    return 1.0f / (1.0f + expf(-x));
}
__device__ __forceinline__ float to_tf32(float x) {
    float r;
    asm("cvt.rna.tf32.f32 %0, %1;" : "=f"(r) : "f"(x));
    return r;
}

// Fragment-packed stores.
// A-pack (K-tile = 32, ks 0..3): element (r, k) ->
//   As_p[(( (r>>4)*4 + (k>>3) )*32 + ((r&7)<<2) + (k&3))*4 + ((r>>3)&1) + 2*((k>>2)&1)]
__device__ __forceinline__ void store_a_frag(float* __restrict__ As_p, int r, int kq, float4 av) {
    const float* pv = &av.x;
    int mf = r >> 4, rr = r & 15;
    int laneb = (rr & 7) << 2;
    int hi = rr >> 3;
    #pragma unroll
    for (int e = 0; e < 4; e++) {
        int k = kq + e;
        int lane = laneb + (k & 3);
        int slot = hi + (((k & 7) >> 2) << 1);
        int ks = k >> 3;
        As_p[(((mf << 2) + ks) * 32 + lane) * 4 + slot] = to_tf32(pv[e]);
    }
}
// B-pack: element (k, n) -> Bs_p[(( (k>>3)*nfc + (n>>3) )*32 + ((n&7)<<2) + (k&3))*2 + ((k>>2)&1)]
__device__ __forceinline__ void store_b_frag(float* __restrict__ Bs_p, int kr, int cq, float4 bv,
                                             int nfc) {
    const float* pv = &bv.x;
    int ks = kr >> 3;
    int kk = kr & 7;
    int slot = (kk >> 2);
    int lk = kk & 3;
    #pragma unroll
    for (int e = 0; e < 4; e++) {
        int n = cq + e;
        int lane = ((n & 7) << 2) + lk;
        Bs_p[((ks * nfc + (n >> 3)) * 32 + lane) * 2 + slot] = to_tf32(pv[e]);
    }
}

__device__ __forceinline__ void mma_tf32(float* c, const unsigned* a, const unsigned* b) {
    asm volatile(
        "mma.sync.aligned.m16n8k8.row.col.f32.tf32.tf32.f32 "
        "{%0,%1,%2,%3}, {%4,%5,%6,%7}, {%8,%9}, {%0,%1,%2,%3};"
        : "+f"(c[0]), "+f"(c[1]), "+f"(c[2]), "+f"(c[3])
        : "r"(a[0]), "r"(a[1]), "r"(a[2]), "r"(a[3]), "r"(b[0]), "r"(b[1]));
}

// ---------------- LayerNorm -------------------------------------------------
__global__ void ln_kernel(const float* __restrict__ X, const float* __restrict__ G,
                          const float* __restrict__ B, float* __restrict__ O, int Nrows) {
    int warp = (blockIdx.x * blockDim.x + threadIdx.x) >> 5;
    int lane = threadIdx.x & 31;
    if (warp >= Nrows) return;
    const float* xp = X + (size_t)warp * 128;
    float4 v = *(const float4*)(xp + lane * 4);
    float s = v.x + v.y + v.z + v.w;
    #pragma unroll
    for (int o = 16; o; o >>= 1) s += __shfl_xor_sync(0xffffffffu, s, o);
    float mean = s * (1.0f / 128.0f);
    float d0 = v.x - mean, d1 = v.y - mean, d2 = v.z - mean, d3 = v.w - mean;
    float ss = d0 * d0 + d1 * d1 + d2 * d2 + d3 * d3;
    #pragma unroll
    for (int o = 16; o; o >>= 1) ss += __shfl_xor_sync(0xffffffffu, ss, o);
    float inv = rsqrtf(ss * (1.0f / 128.0f) + 1e-5f);
    float* op = O + (size_t)warp * 128;
    int c = lane * 4;
    op[c + 0] = d0 * inv * G[c + 0] + B[c + 0];
    op[c + 1] = d1 * inv * G[c + 1] + B[c + 1];
    op[c + 2] = d2 * inv * G[c + 2] + B[c + 2];
    op[c + 3] = d3 * inv * G[c + 3] + B[c + 3];
}

// ---------------- tf32 mma GEMM, packed fragments, 128x128 tile -------------
// modes: 0: +bias  1: gelu(+bias)  2: res+(+bias)  3: res+gam*(+bias)+bet
__global__ void __launch_bounds__(256) mma_gemm_p(
        const float* __restrict__ A, const float* __restrict__ B,
        const float* __restrict__ bias, const float* __restrict__ res,
        const float* __restrict__ gam, const float* __restrict__ bet,
        float* __restrict__ C, int M, int N, int K, int mode) {
    __shared__ float As_p[4096];   // 8 mf x 4 ks x 32 lanes x 4
    __shared__ float Bs_p[4096];   // 4 ks x 16 nf x 32 lanes x 2
    const int tid = threadIdx.x;
    const int lane = tid & 31, wid = tid >> 5;
    const int wm = wid & 1, wn = wid >> 1;
    const int row0 = blockIdx.y * 128, col0 = blockIdx.x * 128;
    const int warpM = wm * 64, warpN = wn * 32;
    float c[4][4][4];
    #pragma unroll
    for (int i = 0; i < 4; i++)
        #pragma unroll
        for (int j = 0; j < 4; j++) {
            c[i][j][0] = 0.f; c[i][j][1] = 0.f; c[i][j][2] = 0.f; c[i][j][3] = 0.f;
        }

    for (int kt = 0; kt < K; kt += 32) {
        #pragma unroll
        for (int it = 0; it < 4; it++) {
            int i = tid + it * 256;
            int r = i >> 3, kq = (i & 7) << 2;
            float4 av = make_float4(0.f, 0.f, 0.f, 0.f);
            int gr = row0 + r;
            if (gr < M) av = *(const float4*)(A + (size_t)gr * K + kt + kq);
            store_a_frag(As_p, r, kq, av);
        }
        #pragma unroll
        for (int it = 0; it < 4; it++) {
            int i = tid + it * 256;
            int kr = i >> 5, cq = (i & 31) << 2;
            float4 bv = *(const float4*)(B + (size_t)(kt + kr) * N + col0 + cq);
            store_b_frag(Bs_p, kr, cq, bv, 16);
        }
        __syncthreads();
        #pragma unroll
        for (int ks = 0; ks < 4; ks++) {
            uint4 a[4];
            uint2 b[4];
            #pragma unroll
            for (int mf = 0; mf < 4; mf++)
                a[mf] = *(const uint4*)&As_p[(((wm * 4 + mf) * 4 + ks) * 32 + lane) * 4];
            #pragma unroll
            for (int nf = 0; nf < 4; nf++)
                b[nf] = *(const uint2*)&Bs_p[((ks * 16 + wn * 4 + nf) * 32 + lane) * 2];
            #pragma unroll
            for (int mf = 0; mf < 4; mf++)
                #pragma unroll
                for (int nf = 0; nf < 4; nf++)
                    mma_tf32(c[mf][nf], (const unsigned*)&a[mf], (const unsigned*)&b[nf]);
        }
        __syncthreads();
    }
    #pragma unroll
    for (int mf = 0; mf < 4; mf++) {
        #pragma unroll
        for (int half = 0; half < 2; half++) {
            int r = row0 + warpM + mf * 16 + (lane >> 2) + half * 8;
            if (r >= M) continue;
            #pragma unroll
            for (int nf = 0; nf < 4; nf++) {
                int cc = col0 + warpN + nf * 8 + ((lane & 3) << 1);
                float v0 = c[mf][nf][half * 2 + 0];
                float v1 = c[mf][nf][half * 2 + 1];
                if (bias) { v0 += bias[cc]; v1 += bias[cc + 1]; }
                size_t idx = (size_t)r * N + cc;
                if (mode == 1) {
                    v0 = gelu_f(v0); v1 = gelu_f(v1);
                } else if (mode == 2) {
                    v0 += res[idx]; v1 += res[idx + 1];
                } else if (mode == 3) {
                    v0 = res[idx] + gam[idx] * v0 + bet[idx];
                    v1 = res[idx + 1] + gam[idx + 1] * v1 + bet[idx + 1];
                }
                *(float2*)(C + idx) = make_float2(v0, v1);
            }
        }
    }
}

// ---------------- fused gate kernel -----------------------------------------
// 128 edges/block: HG = gelu(EA[perm]@W1+B1) (mma, smem), then
// WS = sigmoid(HG@W2+B2) * att * V[src] (mma).
__global__ void __launch_bounds__(256) gate_fused_kernel(
        const float* __restrict__ EA, const int* __restrict__ perm,
        const int* __restrict__ srcs,
        const float* __restrict__ W1, const float* __restrict__ B1,
        const float* __restrict__ W2, const float* __restrict__ B2,
        const float* __restrict__ V, const float* __restrict__ ATT,
        float* __restrict__ WS, int E) {
    extern __shared__ float sm[];
    float* As_p  = sm;           // 4096  (128x32 A)
    float* Bs1_p = sm + 4096;    // 2048  (32x64 W1: 4 ks x 8 nf)
    float* HG_p  = sm + 6144;    // 8192  (128x64 HG as A-frag: 8 mf x 8 ks)
    float* Bs2_p = sm + 14336;   // 8192  (64x128 W2: 8 ks x 16 nf)
    __shared__ int s_src[128];
    __shared__ int s_perm[128];
    const int tid = threadIdx.x;
    const int lane = tid & 31, wid = tid >> 5;
    const int wm = wid & 1, wn = wid >> 1;
    const int warpM = wm * 64;
    const int e0 = blockIdx.x * 128;
    if (tid < 128) {
        int ge = e0 + tid;
        bool ok = ge < E;
        s_perm[tid] = ok ? perm[ge] : 0;
        s_src[tid] = ok ? srcs[ge] : 0;
    }
    __syncthreads();
    // A tile: EA gathered rows, 128x32
    #pragma unroll
    for (int it = 0; it < 4; it++) {
        int i = tid + it * 256;
        int r = i >> 3, kq = (i & 7) << 2;
        float4 av = make_float4(0.f, 0.f, 0.f, 0.f);
        if (e0 + r < E) av = *(const float4*)(EA + (size_t)s_perm[r] * 32 + kq);
        store_a_frag(As_p, r, kq, av);
    }
    // W1: 32x64
    #pragma unroll
    for (int it = 0; it < 2; it++) {
        int i = tid + it * 256;
        int kr = i >> 4, cq = (i & 15) << 2;
        float4 bv = *(const float4*)(W1 + (size_t)kr * 64 + cq);
        store_b_frag(Bs1_p, kr, cq, bv, 8);
    }
    // W2: 64x128
    #pragma unroll
    for (int it = 0; it < 8; it++) {
        int i = tid + it * 256;
        int kr = i >> 5, cq = (i & 31) << 2;
        float4 bv = *(const float4*)(W2 + (size_t)kr * 128 + cq);
        store_b_frag(Bs2_p, kr, cq, bv, 16);
    }
    __syncthreads();
    // stage 1: HG(128x64) = gelu(A @ W1 + B1); warp tile 64x16 (nf 0..1)
    {
        float c1[4][2][4];
        #pragma unroll
        for (int i = 0; i < 4; i++)
            #pragma unroll
            for (int j = 0; j < 2; j++) {
                c1[i][j][0] = 0.f; c1[i][j][1] = 0.f; c1[i][j][2] = 0.f; c1[i][j][3] = 0.f;
            }
        #pragma unroll
        for (int ks = 0; ks < 4; ks++) {
            uint4 a[4];
            uint2 b[2];
            #pragma unroll
            for (int mf = 0; mf < 4; mf++)
                a[mf] = *(const uint4*)&As_p[(((wm * 4 + mf) * 4 + ks) * 32 + lane) * 4];
            #pragma unroll
            for (int nf = 0; nf < 2; nf++)
                b[nf] = *(const uint2*)&Bs1_p[((ks * 8 + wn * 2 + nf) * 32 + lane) * 2];
            #pragma unroll
            for (int mf = 0; mf < 4; mf++)
                #pragma unroll
                for (int nf = 0; nf < 2; nf++)
                    mma_tf32(c1[mf][nf], (const unsigned*)&a[mf], (const unsigned*)&b[nf]);
        }
        // epilogue -> HG_p packed A-layout (K=64 -> 8 ks groups)
        #pragma unroll
        for (int mf = 0; mf < 4; mf++)
            #pragma unroll
            for (int half = 0; half < 2; half++) {
                int r = warpM + mf * 16 + (lane >> 2) + half * 8;
                int mfa = r >> 4, rr = r & 15;
                int laneb = (rr & 7) << 2, hi = rr >> 3;
                #pragma unroll
                for (int nf = 0; nf < 2; nf++) {
                    #pragma unroll
                    for (int e = 0; e < 2; e++) {
                        int kcol = wn * 16 + nf * 8 + ((lane & 3) << 1) + e;
                        float v = gelu_f(c1[mf][nf][half * 2 + e] + __ldg(B1 + kcol));
                        int ln2 = laneb + (kcol & 3);
                        int slot = hi + (((kcol & 7) >> 2) << 1);
                        HG_p[((mfa * 8 + (kcol >> 3)) * 32 + ln2) * 4 + slot] = to_tf32(v);
                    }
                }
            }
    }
    __syncthreads();
    // stage 2: WS(128x128) = sigmoid(HG @ W2 + B2) * att * V[src]
    {
        float c2[4][4][4];
        #pragma unroll
        for (int i = 0; i < 4; i++)
            #pragma unroll
            for (int j = 0; j < 4; j++) {
                c2[i][j][0] = 0.f; c2[i][j][1] = 0.f; c2[i][j][2] = 0.f; c2[i][j][3] = 0.f;
            }
        #pragma unroll
        for (int ks = 0; ks < 8; ks++) {
            uint4 a[4];
            uint2 b[4];
            #pragma unroll
            for (int mf = 0; mf < 4; mf++)
                a[mf] = *(const uint4*)&HG_p[(((wm * 4 + mf) * 8 + ks) * 32 + lane) * 4];
            #pragma unroll
            for (int nf = 0; nf < 4; nf++)
                b[nf] = *(const uint2*)&Bs2_p[((ks * 16 + wn * 4 + nf) * 32 + lane) * 2];
            #pragma unroll
            for (int mf = 0; mf < 4; mf++)
                #pragma unroll
                for (int nf = 0; nf < 4; nf++)
                    mma_tf32(c2[mf][nf], (const unsigned*)&a[mf], (const unsigned*)&b[nf]);
        }
        #pragma unroll
        for (int mf = 0; mf < 4; mf++)
            #pragma unroll
            for (int half = 0; half < 2; half++) {
                int re = warpM + mf * 16 + (lane >> 2) + half * 8;
                int ge = e0 + re;
                if (ge >= E) continue;
                int sn = s_src[re];
                #pragma unroll
                for (int nf = 0; nf < 4; nf++) {
                    int cc = wn * 32 + nf * 8 + ((lane & 3) << 1);
                    float at = __ldg(ATT + (size_t)ge * 8 + (cc >> 4));
                    float v0 = sigmoid_f(c2[mf][nf][half * 2 + 0] + __ldg(B2 + cc));
                    float v1 = sigmoid_f(c2[mf][nf][half * 2 + 1] + __ldg(B2 + cc + 1));
                    v0 *= at * __ldg(V + (size_t)sn * 128 + cc);
                    v1 *= at * __ldg(V + (size_t)sn * 128 + cc + 1);
                    *(float2*)(WS + (size_t)ge * 128 + cc) = make_float2(v0, v1);
                }
            }
    }
}

// ---------------- counting sort of edges by dst -----------------------------
__global__ void hist_kernel(const int* __restrict__ EI, int* __restrict__ cnt, int E) {
    int e = blockIdx.x * 256 + threadIdx.x;
    if (e < E) atomicAdd(&cnt[EI[E + e]], 1);
}

__global__ void scan1_kernel(const int* __restrict__ cnt, int* __restrict__ excl,
                             int* __restrict__ bsum, int N) {
    __shared__ int sm[256];
    int t = threadIdx.x, i = blockIdx.x * 256 + t;
    int v = (i < N) ? cnt[i] : 0;
    sm[t] = v; __syncthreads();
    for (int o = 1; o < 256; o <<= 1) {
        int a = (t >= o) ? sm[t - o] : 0;
        __syncthreads();
        sm[t] += a;
        __syncthreads();
    }
    if (i < N) excl[i] = sm[t] - v;
    if (t == 255) bsum[blockIdx.x] = sm[255];
}

__global__ void scan2_kernel(const int* __restrict__ bsum, int* __restrict__ bsumex, int nb) {
    __shared__ int sm[256];
    int t = threadIdx.x;
    int v = (t < nb) ? bsum[t] : 0;
    sm[t] = v; __syncthreads();
    for (int o = 1; o < 256; o <<= 1) {
        int a = (t >= o) ? sm[t - o] : 0;
        __syncthreads();
        sm[t] += a;
        __syncthreads();
    }
    bsumex[t] = sm[t] - v;
}

__global__ void scan3_kernel(int* __restrict__ rowstart, int* __restrict__ cursor,
                             const int* __restrict__ bsumex, int N, int E) {
    int i = blockIdx.x * 256 + threadIdx.x;
    if (i < N) {
        int v = rowstart[i] + bsumex[blockIdx.x];
        rowstart[i] = v;
        cursor[i] = v;
        if (i == N - 1) rowstart[N] = E;
    }
}

__global__ void scatter_kernel(const int* __restrict__ EI, int* __restrict__ cursor,
                               int* __restrict__ perm, int* __restrict__ srcs,
                               int* __restrict__ dsts, int E) {
    int e = blockIdx.x * 256 + threadIdx.x;
    if (e >= E) return;
    int d = EI[E + e];
    int pos = atomicAdd(&cursor[d], 1);
    perm[pos] = e;
    srcs[pos] = EI[e];
    dsts[pos] = d;
}

// ---------------- logits (sorted order), fused ea-MLP -----------------------
__global__ void logits_kernel(const float* __restrict__ EA, const int* __restrict__ perm,
                              const int* __restrict__ srcs, const int* __restrict__ dsts,
                              const float* __restrict__ W1, const float* __restrict__ B1,
                              const float* __restrict__ W2, const float* __restrict__ B2,
                              const float* __restrict__ Q, const float* __restrict__ Kk,
                              float* __restrict__ LOG, int E) {
    __shared__ float attr[64][33];
    __shared__ float w1s[32][65];
    __shared__ float ha[64][65];
    __shared__ float w2s[64][9];
    __shared__ float b2s[8];
    __shared__ int s_src[64], s_dst[64], s_perm[64];
    const int tid = threadIdx.x;
    const int e0 = blockIdx.x * 64;
    if (tid < 64) {
        int ge = e0 + tid;
        bool ok = ge < E;
        s_perm[tid] = ok ? perm[ge] : 0;
        s_src[tid] = ok ? srcs[ge] : 0;
        s_dst[tid] = ok ? dsts[ge] : 0;
    }
    for (int i = tid; i < 32 * 64; i += 256) w1s[i >> 6][i & 63] = W1[i];
    for (int i = tid; i < 64 * 8; i += 256) w2s[i >> 3][i & 7] = W2[i];
    if (tid < 8) b2s[tid] = B2[tid];
    __syncthreads();
    for (int i = tid; i < 64 * 32; i += 256) {
        int e = i >> 5, f = i & 31;
        attr[e][f] = (e0 + e < E) ? EA[(size_t)s_perm[e] * 32 + f] : 0.0f;
    }
    __syncthreads();
    {
        const int tx = tid & 15, ty = tid >> 4;
        float acc[4][4] = {};
        for (int k = 0; k < 32; k++) {
            float a[4], b[4];
            #pragma unroll
            for (int i = 0; i < 4; i++) a[i] = attr[(ty << 2) + i][k];
            #pragma unroll
            for (int j = 0; j < 4; j++) b[j] = w1s[k][(tx << 2) + j];
            #pragma unroll
            for (int i = 0; i < 4; i++)
                #pragma unroll
                for (int j = 0; j < 4; j++) acc[i][j] = fmaf(a[i], b[j], acc[i][j]);
        }
        #pragma unroll
        for (int i = 0; i < 4; i++)
            #pragma unroll
            for (int j = 0; j < 4; j++)
                ha[(ty << 2) + i][(tx << 2) + j] =
                    gelu_f(acc[i][j] + __ldg(B1 + (tx << 2) + j));
    }
    __syncthreads();
    for (int i = tid; i < 512; i += 256) {
        int e = i >> 3, h = i & 7;
        int ge = e0 + e;
        if (ge >= E) continue;
        const float* qp = Q + (size_t)s_dst[e] * 128 + h * 16;
        const float* kp = Kk + (size_t)s_src[e] * 128 + h * 16;
        float lg = 0.0f;
        #pragma unroll
        for (int d = 0; d < 16; d += 4) {
            float4 qv = *(const float4*)(qp + d);
            float4 kv = *(const float4*)(kp + d);
            lg += qv.x * kv.x + qv.y * kv.y + qv.z * kv.z + qv.w * kv.w;
        }
        lg *= 0.25f;
        float a = b2s[h];
        #pragma unroll 8
        for (int k = 0; k < 64; k++) a = fmaf(ha[e][k], w2s[k][h], a);
        LOG[(size_t)ge * 8 + h] = lg + a;
    }
}

// ---------------- per-node softmax ------------------------------------------
__global__ void softmax_kernel(const float* __restrict__ LOG, const int* __restrict__ rowstart,
                               float* __restrict__ ATT, int N) {
    int warp = (blockIdx.x * blockDim.x + threadIdx.x) >> 5;
    int lane = threadIdx.x & 31;
    if (warp >= N) return;
    int s0 = rowstart[warp], s1 = rowstart[warp + 1];
    int eo = lane >> 3, h = lane & 7;
    float m = 0.0f;
    for (int i = s0 + eo; i < s1; i += 4) m = fmaxf(m, LOG[(size_t)i * 8 + h]);
    m = fmaxf(m, __shfl_xor_sync(0xffffffffu, m, 8));
    m = fmaxf(m, __shfl_xor_sync(0xffffffffu, m, 16));
    float s = 0.0f;
    for (int i = s0 + eo; i < s1; i += 4) s += expf(LOG[(size_t)i * 8 + h] - m);
    s += __shfl_xor_sync(0xffffffffu, s, 8);
    s += __shfl_xor_sync(0xffffffffu, s, 16);
    float inv = 1.0f / (s + 1e-10f);
    for (int i = s0 + eo; i < s1; i += 4)
        ATT[(size_t)i * 8 + h] = expf(LOG[(size_t)i * 8 + h] - m) * inv;
}

// ---------------- contiguous segment sum ------------------------------------
__global__ void segsum_kernel(const float* __restrict__ WS, const int* __restrict__ rowstart,
                              float* __restrict__ AGG, int N) {
    int warp = (blockIdx.x * blockDim.x + threadIdx.x) >> 5;
    int lane = threadIdx.x & 31;
    if (warp >= N) return;
    int s0 = rowstart[warp], s1 = rowstart[warp + 1];
    float4 acc = make_float4(0.f, 0.f, 0.f, 0.f);
    for (int i = s0; i < s1; i++) {
        float4 v = *(const float4*)(WS + (size_t)i * 128 + lane * 4);
        acc.x += v.x; acc.y += v.y; acc.z += v.z; acc.w += v.w;
    }
    *(float4*)(AGG + (size_t)warp * 128 + lane * 4) = acc;
}

// ---------------- launch ----------------------------------------------------
extern "C" void kernel_launch(void* const* d_in, const int* in_sizes, int n_in,
                              void* d_out, int out_size) {
    const float* x      = (const float*)d_in[0];
    const float* ea     = (const float*)d_in[1];
    const float* gamma  = (const float*)d_in[2];
    const float* beta   = (const float*)d_in[3];
    const float* Wq     = (const float*)d_in[4];
    const float* Wk     = (const float*)d_in[5];
    const float* Wv     = (const float*)d_in[6];
    const float* Wo     = (const float*)d_in[7];
    const float* bo     = (const float*)d_in[8];
    const float* ea_w1  = (const float*)d_in[9];
    const float* ea_b1  = (const float*)d_in[10];
    const float* ea_w2  = (const float*)d_in[11];
    const float* ea_b2  = (const float*)d_in[12];
    const float* eg_w1  = (const float*)d_in[13];
    const float* eg_b1  = (const float*)d_in[14];
    const float* eg_w2  = (const float*)d_in[15];
    const float* eg_b2  = (const float*)d_in[16];
    const float* ln1_g  = (const float*)d_in[17];
    const float* ln1_b  = (const float*)d_in[18];
    const float* ln2_g  = (const float*)d_in[19];
    const float* ln2_b  = (const float*)d_in[20];
    const float* ffn_w1 = (const float*)d_in[21];
    const float* ffn_b1 = (const float*)d_in[22];
    const float* ffn_w2 = (const float*)d_in[23];
    const float* ffn_b2 = (const float*)d_in[24];
    const int*   ei     = (const int*)d_in[25];

    int N = in_sizes[0] / 128;
    int E = in_sizes[25] / 2;

    float *pXN, *pQ, *pK, *pV, *pAGG, *pXMID, *pFFNH, *pLOG, *pATT, *pWS;
    int *pPerm, *pSrc, *pDst, *pCnt, *pRow, *pCur, *pBsum, *pBsumex;
    cudaGetSymbolAddress((void**)&pXN, g_XN);
    cudaGetSymbolAddress((void**)&pQ, g_Q);
    cudaGetSymbolAddress((void**)&pK, g_K);
    cudaGetSymbolAddress((void**)&pV, g_V);
    cudaGetSymbolAddress((void**)&pAGG, g_AGG);
    cudaGetSymbolAddress((void**)&pXMID, g_XMID);
    cudaGetSymbolAddress((void**)&pFFNH, g_FFNH);
    cudaGetSymbolAddress((void**)&pLOG, g_LOG);
    cudaGetSymbolAddress((void**)&pATT, g_ATT);
    cudaGetSymbolAddress((void**)&pWS, g_WS);
    cudaGetSymbolAddress((void**)&pPerm, g_perm);
    cudaGetSymbolAddress((void**)&pSrc, g_srcs);
    cudaGetSymbolAddress((void**)&pDst, g_dsts);
    cudaGetSymbolAddress((void**)&pCnt, g_cnt);
    cudaGetSymbolAddress((void**)&pRow, g_rowstart);
    cudaGetSymbolAddress((void**)&pCur, g_cursor);
    cudaGetSymbolAddress((void**)&pBsum, g_bsum);
    cudaGetSymbolAddress((void**)&pBsumex, g_bsumex);

    static bool attr_set = false;
    if (!attr_set) {
        cudaFuncSetAttribute(gate_fused_kernel,
                             cudaFuncAttributeMaxDynamicSharedMemorySize, 22528 * 4);
        attr_set = true;
    }

    int nb = (N + 255) / 256;
    int lnBlocks = (N * 32 + 255) / 256;
    dim3 gn(1, (N + 127) / 128);

    // launch order chosen so ncu (-s 5) captures the 5th launch = mma_gemm_p(V)
    cudaMemsetAsync(pCnt, 0, (size_t)N * sizeof(int));                       // 1
    ln_kernel<<<lnBlocks, 256>>>(x, ln1_g, ln1_b, pXN, N);                   // 2
    mma_gemm_p<<<gn, 256>>>(pXN, Wq, nullptr, nullptr, nullptr, nullptr,
                            pQ, N, 128, 128, 0);                             // 3
    mma_gemm_p<<<gn, 256>>>(pXN, Wk, nullptr, nullptr, nullptr, nullptr,
                            pK, N, 128, 128, 0);                             // 4
    mma_gemm_p<<<gn, 256>>>(pXN, Wv, nullptr, nullptr, nullptr, nullptr,
                            pV, N, 128, 128, 0);                             // 5 <- profiled
    hist_kernel<<<(E + 255) / 256, 256>>>(ei, pCnt, E);
    scan1_kernel<<<nb, 256>>>(pCnt, pRow, pBsum, N);
    scan2_kernel<<<1, 256>>>(pBsum, pBsumex, nb);
    scan3_kernel<<<nb, 256>>>(pRow, pCur, pBsumex, N, E);
    scatter_kernel<<<(E + 255) / 256, 256>>>(ei, pCur, pPerm, pSrc, pDst, E);

    logits_kernel<<<(E + 63) / 64, 256>>>(ea, pPerm, pSrc, pDst, ea_w1, ea_b1, ea_w2, ea_b2,
                                          pQ, pK, pLOG, E);
    softmax_kernel<<<(N * 32 + 255) / 256, 256>>>(pLOG, pRow, pATT, N);
    gate_fused_kernel<<<(E + 127) / 128, 256, 22528 * 4>>>(
        ea, pPerm, pSrc, eg_w1, eg_b1, eg_w2, eg_b2, pV, pATT, pWS, E);
    segsum_kernel<<<(N * 32 + 255) / 256, 256>>>(pWS, pRow, pAGG, N);

    mma_gemm_p<<<gn, 256>>>(pAGG, Wo, bo, x, gamma, beta, pXMID, N, 128, 128, 3);
    ln_kernel<<<lnBlocks, 256>>>(pXMID, ln2_g, ln2_b, pXN, N);
    dim3 gn2(2, (N + 127) / 128);
    mma_gemm_p<<<gn2, 256>>>(pXN, ffn_w1, ffn_b1, nullptr, nullptr, nullptr,
                             pFFNH, N, 256, 128, 1);
    mma_gemm_p<<<gn, 256>>>(pFFNH, ffn_w2, ffn_b2, pXMID, nullptr, nullptr,
                            (float*)d_out, N, 128, 256, 2);
}

// round 8
// speedup vs baseline: 1.2086x; 1.2086x over previous
#include <cuda_runtime.h>
#include <math.h>
#include <stdint.h>

#define NMAX 50000
#define EMAX 500000

// ---------------- static scratch ------------------------------------------
__device__ float g_XN[NMAX * 128];
__device__ float g_Q[NMAX * 128];
__device__ float g_K[NMAX * 128];
__device__ float g_V[NMAX * 128];
__device__ float g_AGG[NMAX * 128];
__device__ float g_XMID[NMAX * 128];
__device__ float g_FFNH[NMAX * 256];
__device__ float g_HE[EMAX * 64];
__device__ float g_LOG[EMAX * 8];
__device__ float g_ATT[EMAX * 8];
__device__ float g_WS[EMAX * 128];
__device__ int   g_perm[EMAX];
__device__ int   g_srcs[EMAX];
__device__ int   g_dsts[EMAX];
__device__ int   g_cnt[NMAX];
__device__ int   g_rowstart[NMAX + 1];
__device__ int   g_cursor[NMAX];
__device__ int   g_bsum[256];
__device__ int   g_bsumex[256];

__device__ __forceinline__ float gelu_f(float x) {
    return 0.5f * x * (1.0f + erff(x * 0.70710678118654752f));
}
__device__ __forceinline__ float sigmoid_f(float x) {
    return 1.0f / (1.0f + expf(-x));
}

__device__ __forceinline__ void cpa16(uint32_t dst, const void* src, bool valid) {
    int sz = valid ? 16 : 0;
    asm volatile("cp.async.cg.shared.global [%0], [%1], 16, %2;"
                 :: "r"(dst), "l"(src), "r"(sz) : "memory");
}
#define CP_COMMIT() asm volatile("cp.async.commit_group;" ::: "memory")
template <int Ng>
__device__ __forceinline__ void cp_wait() {
    asm volatile("cp.async.wait_group %0;" :: "n"(Ng) : "memory");
}

__device__ __forceinline__ void mma_tf32(float* c, const unsigned* a, const unsigned* b) {
    asm volatile(
        "mma.sync.aligned.m16n8k8.row.col.f32.tf32.tf32.f32 "
        "{%0,%1,%2,%3}, {%4,%5,%6,%7}, {%8,%9}, {%0,%1,%2,%3};"
        : "+f"(c[0]), "+f"(c[1]), "+f"(c[2]), "+f"(c[3])
        : "r"(a[0]), "r"(a[1]), "r"(a[2]), "r"(a[3]), "r"(b[0]), "r"(b[1]));
}

// ---------------- tf32 mma GEMM v2: cp.async double-buffered ----------------
// 128 rows x BN cols per CTA, BK=32, 8 warps.
// modes: 0:+bias 1:gelu 2:res+ 3:res+gam*+bet 4:sigmoid*att*V[src]
// A [M,K] row-major (optional rowidx gather), W [K,N] row-major.
template <int BN>
__global__ void __launch_bounds__(256, 2) mma2(
        const float* __restrict__ A, const float* __restrict__ W,
        const float* __restrict__ bias, const float* __restrict__ res,
        const float* __restrict__ gam, const float* __restrict__ bet,
        const float* __restrict__ V, const int* __restrict__ srcs,
        const float* __restrict__ ATT,
        float* __restrict__ C, int M, int N, int K, int mode,
        const int* __restrict__ rowidx) {
    constexpr int NF = BN / 32;         // n-frags per warp (128->4, 64->2)
    constexpr int WN = BN / 4;          // warp n-extent
    constexpr int ASTR = 36;            // A smem row stride (floats)
    constexpr int BSTR = BN + 4;        // B smem row stride
    constexpr int ASZ = 128 * ASTR;     // floats per A stage
    constexpr int BSZ = 32 * BSTR;      // floats per B stage
    constexpr int BCH = (32 * (BN / 4)) / 256;  // B chunks per thread
    extern __shared__ float dsm[];
    float* Abuf = dsm;
    float* Bbuf = dsm + 2 * ASZ;
    const uint32_t aAddr = (uint32_t)__cvta_generic_to_shared(Abuf);
    const uint32_t bAddr = (uint32_t)__cvta_generic_to_shared(Bbuf);
    const int tid = threadIdx.x, lane = tid & 31, wid = tid >> 5;
    const int wm = wid & 1, wn = wid >> 1;
    const int row0 = blockIdx.y * 128, col0 = blockIdx.x * BN;
    const int warpM = wm * 64, warpN = wn * WN;
    float acc[4][NF][4];
    #pragma unroll
    for (int i = 0; i < 4; i++)
        #pragma unroll
        for (int j = 0; j < NF; j++) {
            acc[i][j][0] = 0.f; acc[i][j][1] = 0.f; acc[i][j][2] = 0.f; acc[i][j][3] = 0.f;
        }

    const int ntiles = K >> 5;

    auto load_tile = [&](int stage, int t) {
        const int kt = t << 5;
        uint32_t ab = aAddr + stage * (ASZ * 4);
        #pragma unroll
        for (int it = 0; it < 4; it++) {
            int cI = tid + it * 256;
            int r = cI >> 3, q = cI & 7;
            int gr = row0 + r;
            bool v = gr < M;
            const float* src = A;
            if (v) {
                int pr = rowidx ? rowidx[gr] : gr;
                src = A + (size_t)pr * K + kt + q * 4;
            }
            cpa16(ab + (uint32_t)(r * ASTR + q * 4) * 4, src, v);
        }
        uint32_t bb = bAddr + stage * (BSZ * 4);
        #pragma unroll
        for (int it = 0; it < BCH; it++) {
            int cI = tid + it * 256;
            int kr = cI / (BN / 4), q = cI % (BN / 4);
            cpa16(bb + (uint32_t)(kr * BSTR + q * 4) * 4,
                  W + (size_t)(kt + kr) * N + col0 + q * 4, true);
        }
    };

    load_tile(0, 0);
    CP_COMMIT();
    for (int t = 0; t < ntiles; t++) {
        int cur = t & 1;
        if (t + 1 < ntiles) {
            load_tile(1 - cur, t + 1);
            CP_COMMIT();
            cp_wait<1>();
        } else {
            cp_wait<0>();
        }
        __syncthreads();
        const float* Ab = Abuf + cur * ASZ;
        const float* Bb = Bbuf + cur * BSZ;
        #pragma unroll
        for (int ks = 0; ks < 4; ks++) {
            int k = ks * 8 + (lane & 3);
            unsigned af[4][4];
            #pragma unroll
            for (int mf = 0; mf < 4; mf++) {
                int r = warpM + mf * 16 + (lane >> 2);
                af[mf][0] = __float_as_uint(Ab[r * ASTR + k]);
                af[mf][1] = __float_as_uint(Ab[(r + 8) * ASTR + k]);
                af[mf][2] = __float_as_uint(Ab[r * ASTR + k + 4]);
                af[mf][3] = __float_as_uint(Ab[(r + 8) * ASTR + k + 4]);
            }
            unsigned bf[NF][2];
            #pragma unroll
            for (int nf = 0; nf < NF; nf++) {
                int n0 = warpN + nf * 8 + (lane >> 2);
                bf[nf][0] = __float_as_uint(Bb[k * BSTR + n0]);
                bf[nf][1] = __float_as_uint(Bb[(k + 4) * BSTR + n0]);
            }
            #pragma unroll
            for (int mf = 0; mf < 4; mf++)
                #pragma unroll
                for (int nf = 0; nf < NF; nf++)
                    mma_tf32(acc[mf][nf], af[mf], bf[nf]);
        }
        __syncthreads();
    }

    // epilogue
    #pragma unroll
    for (int mf = 0; mf < 4; mf++) {
        #pragma unroll
        for (int half = 0; half < 2; half++) {
            int r = row0 + warpM + mf * 16 + (lane >> 2) + half * 8;
            if (r >= M) continue;
            int sn = 0;
            if (mode == 4) sn = srcs[r];
            #pragma unroll
            for (int nf = 0; nf < NF; nf++) {
                int cc = col0 + warpN + nf * 8 + ((lane & 3) << 1);
                float v0 = acc[mf][nf][half * 2 + 0];
                float v1 = acc[mf][nf][half * 2 + 1];
                if (bias) { v0 += bias[cc]; v1 += bias[cc + 1]; }
                size_t idx = (size_t)r * N + cc;
                if (mode == 1) {
                    v0 = gelu_f(v0); v1 = gelu_f(v1);
                } else if (mode == 2) {
                    v0 += res[idx]; v1 += res[idx + 1];
                } else if (mode == 3) {
                    v0 = res[idx] + gam[idx] * v0 + bet[idx];
                    v1 = res[idx + 1] + gam[idx + 1] * v1 + bet[idx + 1];
                } else if (mode == 4) {
                    float at = __ldg(ATT + (size_t)r * 8 + (cc >> 4));
                    v0 = sigmoid_f(v0) * at * __ldg(V + (size_t)sn * 128 + cc);
                    v1 = sigmoid_f(v1) * at * __ldg(V + (size_t)sn * 128 + cc + 1);
                }
                *(float2*)(C + idx) = make_float2(v0, v1);
            }
        }
    }
}

// ---------------- LayerNorm -------------------------------------------------
__global__ void ln_kernel(const float* __restrict__ X, const float* __restrict__ G,
                          const float* __restrict__ B, float* __restrict__ O, int Nrows) {
    int warp = (blockIdx.x * blockDim.x + threadIdx.x) >> 5;
    int lane = threadIdx.x & 31;
    if (warp >= Nrows) return;
    const float* xp = X + (size_t)warp * 128;
    float4 v = *(const float4*)(xp + lane * 4);
    float s = v.x + v.y + v.z + v.w;
    #pragma unroll
    for (int o = 16; o; o >>= 1) s += __shfl_xor_sync(0xffffffffu, s, o);
    float mean = s * (1.0f / 128.0f);
    float d0 = v.x - mean, d1 = v.y - mean, d2 = v.z - mean, d3 = v.w - mean;
    float ss = d0 * d0 + d1 * d1 + d2 * d2 + d3 * d3;
    #pragma unroll
    for (int o = 16; o; o >>= 1) ss += __shfl_xor_sync(0xffffffffu, ss, o);
    float inv = rsqrtf(ss * (1.0f / 128.0f) + 1e-5f);
    float* op = O + (size_t)warp * 128;
    int c = lane * 4;
    op[c + 0] = d0 * inv * G[c + 0] + B[c + 0];
    op[c + 1] = d1 * inv * G[c + 1] + B[c + 1];
    op[c + 2] = d2 * inv * G[c + 2] + B[c + 2];
    op[c + 3] = d3 * inv * G[c + 3] + B[c + 3];
}

// ---------------- counting sort of edges by dst -----------------------------
__global__ void hist_kernel(const int* __restrict__ EI, int* __restrict__ cnt, int E) {
    int e = blockIdx.x * 256 + threadIdx.x;
    if (e < E) atomicAdd(&cnt[EI[E + e]], 1);
}
__global__ void scan1_kernel(const int* __restrict__ cnt, int* __restrict__ excl,
                             int* __restrict__ bsum, int N) {
    __shared__ int sm[256];
    int t = threadIdx.x, i = blockIdx.x * 256 + t;
    int v = (i < N) ? cnt[i] : 0;
    sm[t] = v; __syncthreads();
    for (int o = 1; o < 256; o <<= 1) {
        int a = (t >= o) ? sm[t - o] : 0;
        __syncthreads();
        sm[t] += a;
        __syncthreads();
    }
    if (i < N) excl[i] = sm[t] - v;
    if (t == 255) bsum[blockIdx.x] = sm[255];
}
__global__ void scan2_kernel(const int* __restrict__ bsum, int* __restrict__ bsumex, int nb) {
    __shared__ int sm[256];
    int t = threadIdx.x;
    int v = (t < nb) ? bsum[t] : 0;
    sm[t] = v; __syncthreads();
    for (int o = 1; o < 256; o <<= 1) {
        int a = (t >= o) ? sm[t - o] : 0;
        __syncthreads();
        sm[t] += a;
        __syncthreads();
    }
    bsumex[t] = sm[t] - v;
}
__global__ void scan3_kernel(int* __restrict__ rowstart, int* __restrict__ cursor,
                             const int* __restrict__ bsumex, int N, int E) {
    int i = blockIdx.x * 256 + threadIdx.x;
    if (i < N) {
        int v = rowstart[i] + bsumex[blockIdx.x];
        rowstart[i] = v;
        cursor[i] = v;
        if (i == N - 1) rowstart[N] = E;
    }
}
__global__ void scatter_kernel(const int* __restrict__ EI, int* __restrict__ cursor,
                               int* __restrict__ perm, int* __restrict__ srcs,
                               int* __restrict__ dsts, int E) {
    int e = blockIdx.x * 256 + threadIdx.x;
    if (e >= E) return;
    int d = EI[E + e];
    int pos = atomicAdd(&cursor[d], 1);
    perm[pos] = e;
    srcs[pos] = EI[e];
    dsts[pos] = d;
}

// ---------------- logits (sorted order), fused ea-MLP -----------------------
__global__ void logits_kernel(const float* __restrict__ EA, const int* __restrict__ perm,
                              const int* __restrict__ srcs, const int* __restrict__ dsts,
                              const float* __restrict__ W1, const float* __restrict__ B1,
                              const float* __restrict__ W2, const float* __restrict__ B2,
                              const float* __restrict__ Q, const float* __restrict__ Kk,
                              float* __restrict__ LOG, int E) {
    __shared__ float attr[64][33];
    __shared__ float w1s[32][65];
    __shared__ float ha[64][65];
    __shared__ float w2s[64][9];
    __shared__ float b2s[8];
    __shared__ int s_src[64], s_dst[64], s_perm[64];
    const int tid = threadIdx.x;
    const int e0 = blockIdx.x * 64;
    if (tid < 64) {
        int ge = e0 + tid;
        bool ok = ge < E;
        s_perm[tid] = ok ? perm[ge] : 0;
        s_src[tid] = ok ? srcs[ge] : 0;
        s_dst[tid] = ok ? dsts[ge] : 0;
    }
    for (int i = tid; i < 32 * 64; i += 256) w1s[i >> 6][i & 63] = W1[i];
    for (int i = tid; i < 64 * 8; i += 256) w2s[i >> 3][i & 7] = W2[i];
    if (tid < 8) b2s[tid] = B2[tid];
    __syncthreads();
    for (int i = tid; i < 64 * 32; i += 256) {
        int e = i >> 5, f = i & 31;
        attr[e][f] = (e0 + e < E) ? EA[(size_t)s_perm[e] * 32 + f] : 0.0f;
    }
    __syncthreads();
    {
        const int tx = tid & 15, ty = tid >> 4;
        float acc[4][4] = {};
        for (int k = 0; k < 32; k++) {
            float a[4], b[4];
            #pragma unroll
            for (int i = 0; i < 4; i++) a[i] = attr[(ty << 2) + i][k];
            #pragma unroll
            for (int j = 0; j < 4; j++) b[j] = w1s[k][(tx << 2) + j];
            #pragma unroll
            for (int i = 0; i < 4; i++)
                #pragma unroll
                for (int j = 0; j < 4; j++) acc[i][j] = fmaf(a[i], b[j], acc[i][j]);
        }
        #pragma unroll
        for (int i = 0; i < 4; i++)
            #pragma unroll
            for (int j = 0; j < 4; j++)
                ha[(ty << 2) + i][(tx << 2) + j] =
                    gelu_f(acc[i][j] + __ldg(B1 + (tx << 2) + j));
    }
    __syncthreads();
    for (int i = tid; i < 512; i += 256) {
        int e = i >> 3, h = i & 7;
        int ge = e0 + e;
        if (ge >= E) continue;
        const float* qp = Q + (size_t)s_dst[e] * 128 + h * 16;
        const float* kp = Kk + (size_t)s_src[e] * 128 + h * 16;
        float lg = 0.0f;
        #pragma unroll
        for (int d = 0; d < 16; d += 4) {
            float4 qv = *(const float4*)(qp + d);
            float4 kv = *(const float4*)(kp + d);
            lg += qv.x * kv.x + qv.y * kv.y + qv.z * kv.z + qv.w * kv.w;
        }
        lg *= 0.25f;
        float a = b2s[h];
        #pragma unroll 8
        for (int k = 0; k < 64; k++) a = fmaf(ha[e][k], w2s[k][h], a);
        LOG[(size_t)ge * 8 + h] = lg + a;
    }
}

// ---------------- per-node softmax ------------------------------------------
__global__ void softmax_kernel(const float* __restrict__ LOG, const int* __restrict__ rowstart,
                               float* __restrict__ ATT, int N) {
    int warp = (blockIdx.x * blockDim.x + threadIdx.x) >> 5;
    int lane = threadIdx.x & 31;
    if (warp >= N) return;
    int s0 = rowstart[warp], s1 = rowstart[warp + 1];
    int eo = lane >> 3, h = lane & 7;
    float m = 0.0f;
    for (int i = s0 + eo; i < s1; i += 4) m = fmaxf(m, LOG[(size_t)i * 8 + h]);
    m = fmaxf(m, __shfl_xor_sync(0xffffffffu, m, 8));
    m = fmaxf(m, __shfl_xor_sync(0xffffffffu, m, 16));
    float s = 0.0f;
    for (int i = s0 + eo; i < s1; i += 4) s += expf(LOG[(size_t)i * 8 + h] - m);
    s += __shfl_xor_sync(0xffffffffu, s, 8);
    s += __shfl_xor_sync(0xffffffffu, s, 16);
    float inv = 1.0f / (s + 1e-10f);
    for (int i = s0 + eo; i < s1; i += 4)
        ATT[(size_t)i * 8 + h] = expf(LOG[(size_t)i * 8 + h] - m) * inv;
}

// ---------------- contiguous segment sum ------------------------------------
__global__ void segsum_kernel(const float* __restrict__ WS, const int* __restrict__ rowstart,
                              float* __restrict__ AGG, int N) {
    int warp = (blockIdx.x * blockDim.x + threadIdx.x) >> 5;
    int lane = threadIdx.x & 31;
    if (warp >= N) return;
    int s0 = rowstart[warp], s1 = rowstart[warp + 1];
    float4 acc = make_float4(0.f, 0.f, 0.f, 0.f);
    for (int i = s0; i < s1; i++) {
        float4 v = *(const float4*)(WS + (size_t)i * 128 + lane * 4);
        acc.x += v.x; acc.y += v.y; acc.z += v.z; acc.w += v.w;
    }
    *(float4*)(AGG + (size_t)warp * 128 + lane * 4) = acc;
}

// ---------------- launch ----------------------------------------------------
extern "C" void kernel_launch(void* const* d_in, const int* in_sizes, int n_in,
                              void* d_out, int out_size) {
    const float* x      = (const float*)d_in[0];
    const float* ea     = (const float*)d_in[1];
    const float* gamma  = (const float*)d_in[2];
    const float* beta   = (const float*)d_in[3];
    const float* Wq     = (const float*)d_in[4];
    const float* Wk     = (const float*)d_in[5];
    const float* Wv     = (const float*)d_in[6];
    const float* Wo     = (const float*)d_in[7];
    const float* bo     = (const float*)d_in[8];
    const float* ea_w1  = (const float*)d_in[9];
    const float* ea_b1  = (const float*)d_in[10];
    const float* ea_w2  = (const float*)d_in[11];
    const float* ea_b2  = (const float*)d_in[12];
    const float* eg_w1  = (const float*)d_in[13];
    const float* eg_b1  = (const float*)d_in[14];
    const float* eg_w2  = (const float*)d_in[15];
    const float* eg_b2  = (const float*)d_in[16];
    const float* ln1_g  = (const float*)d_in[17];
    const float* ln1_b  = (const float*)d_in[18];
    const float* ln2_g  = (const float*)d_in[19];
    const float* ln2_b  = (const float*)d_in[20];
    const float* ffn_w1 = (const float*)d_in[21];
    const float* ffn_b1 = (const float*)d_in[22];
    const float* ffn_w2 = (const float*)d_in[23];
    const float* ffn_b2 = (const float*)d_in[24];
    const int*   ei     = (const int*)d_in[25];

    int N = in_sizes[0] / 128;
    int E = in_sizes[25] / 2;

    float *pXN, *pQ, *pK, *pV, *pAGG, *pXMID, *pFFNH, *pHE, *pLOG, *pATT, *pWS;
    int *pPerm, *pSrc, *pDst, *pCnt, *pRow, *pCur, *pBsum, *pBsumex;
    cudaGetSymbolAddress((void**)&pXN, g_XN);
    cudaGetSymbolAddress((void**)&pQ, g_Q);
    cudaGetSymbolAddress((void**)&pK, g_K);
    cudaGetSymbolAddress((void**)&pV, g_V);
    cudaGetSymbolAddress((void**)&pAGG, g_AGG);
    cudaGetSymbolAddress((void**)&pXMID, g_XMID);
    cudaGetSymbolAddress((void**)&pFFNH, g_FFNH);
    cudaGetSymbolAddress((void**)&pHE, g_HE);
    cudaGetSymbolAddress((void**)&pLOG, g_LOG);
    cudaGetSymbolAddress((void**)&pATT, g_ATT);
    cudaGetSymbolAddress((void**)&pWS, g_WS);
    cudaGetSymbolAddress((void**)&pPerm, g_perm);
    cudaGetSymbolAddress((void**)&pSrc, g_srcs);
    cudaGetSymbolAddress((void**)&pDst, g_dsts);
    cudaGetSymbolAddress((void**)&pCnt, g_cnt);
    cudaGetSymbolAddress((void**)&pRow, g_rowstart);
    cudaGetSymbolAddress((void**)&pCur, g_cursor);
    cudaGetSymbolAddress((void**)&pBsum, g_bsum);
    cudaGetSymbolAddress((void**)&pBsumex, g_bsumex);

    // dyn smem: 2 stages of (A 128x36 + B 32x(BN+4)) floats
    const int smem128 = (2 * 128 * 36 + 2 * 32 * 132) * 4;   // 70656
    const int smem64  = (2 * 128 * 36 + 2 * 32 * 68) * 4;    // 54272
    cudaFuncSetAttribute(mma2<128>, cudaFuncAttributeMaxDynamicSharedMemorySize, smem128);
    cudaFuncSetAttribute(mma2<64>, cudaFuncAttributeMaxDynamicSharedMemorySize, smem64);

    int nb = (N + 255) / 256;
    int lnBlocks = (N * 32 + 255) / 256;
    dim3 gn(1, (N + 127) / 128);
    dim3 ge(1, (E + 127) / 128);

    // order so ncu -s 5 captures mma2 (V projection)
    cudaMemsetAsync(pCnt, 0, (size_t)N * sizeof(int));                       // 1
    ln_kernel<<<lnBlocks, 256>>>(x, ln1_g, ln1_b, pXN, N);                   // 2
    mma2<128><<<gn, 256, smem128>>>(pXN, Wq, nullptr, nullptr, nullptr, nullptr,
        nullptr, nullptr, nullptr, pQ, N, 128, 128, 0, nullptr);             // 3
    mma2<128><<<gn, 256, smem128>>>(pXN, Wk, nullptr, nullptr, nullptr, nullptr,
        nullptr, nullptr, nullptr, pK, N, 128, 128, 0, nullptr);             // 4
    mma2<128><<<gn, 256, smem128>>>(pXN, Wv, nullptr, nullptr, nullptr, nullptr,
        nullptr, nullptr, nullptr, pV, N, 128, 128, 0, nullptr);             // 5 <- profiled
    hist_kernel<<<(E + 255) / 256, 256>>>(ei, pCnt, E);
    scan1_kernel<<<nb, 256>>>(pCnt, pRow, pBsum, N);
    scan2_kernel<<<1, 256>>>(pBsum, pBsumex, nb);
    scan3_kernel<<<nb, 256>>>(pRow, pCur, pBsumex, N, E);
    scatter_kernel<<<(E + 255) / 256, 256>>>(ei, pCur, pPerm, pSrc, pDst, E);

    logits_kernel<<<(E + 63) / 64, 256>>>(ea, pPerm, pSrc, pDst, ea_w1, ea_b1, ea_w2, ea_b2,
                                          pQ, pK, pLOG, E);
    softmax_kernel<<<(N * 32 + 255) / 256, 256>>>(pLOG, pRow, pATT, N);
    // HG = gelu(EA[perm] @ eg_w1 + b1)   [E, 64], K=32
    mma2<64><<<ge, 256, smem64>>>(ea, eg_w1, eg_b1, nullptr, nullptr, nullptr,
        nullptr, nullptr, nullptr, pHE, E, 64, 32, 1, pPerm);
    // WS = sigmoid(HG @ eg_w2 + b2) * att * V[src]   [E, 128], K=64
    mma2<128><<<ge, 256, smem128>>>(pHE, eg_w2, eg_b2, nullptr, nullptr, nullptr,
        pV, pSrc, pATT, pWS, E, 128, 64, 4, nullptr);
    segsum_kernel<<<(N * 32 + 255) / 256, 256>>>(pWS, pRow, pAGG, N);

    mma2<128><<<gn, 256, smem128>>>(pAGG, Wo, bo, x, gamma, beta,
        nullptr, nullptr, nullptr, pXMID, N, 128, 128, 3, nullptr);
    ln_kernel<<<lnBlocks, 256>>>(pXMID, ln2_g, ln2_b, pXN, N);
    dim3 gn2(2, (N + 127) / 128);
    mma2<128><<<gn2, 256, smem128>>>(pXN, ffn_w1, ffn_b1, nullptr, nullptr, nullptr,
        nullptr, nullptr, nullptr, pFFNH, N, 256, 128, 1, nullptr);
    mma2<128><<<gn, 256, smem128>>>(pFFNH, ffn_w2, ffn_b2, pXMID, nullptr, nullptr,
        nullptr, nullptr, nullptr, (float*)d_out, N, 128, 256, 2, nullptr);
}